// round 11
// baseline (speedup 1.0000x reference)
#include <cuda_runtime.h>
#include <cuda_fp16.h>
#include <cuda_bf16.h>
#include <cstdint>

// HalfKP NNUE forward. Three-kernel graph:
//  1) convert_tables: fp32 tables -> fp16 __device__ scratch (42MB, L2-resident)
//  2) gather_kernel:  one warp per (position, table) embedding-bag sum -> fp16 x[B][512]
//  3) mlp_kernel:     fc1+fc2+fc3 from x, 8 positions per block
//
// Inputs (metadata order):
//  0 white_indices int32 [B*BAG]   1 white_offsets int64 [B] (unused)
//  2 black_indices int32 [B*BAG]   3 black_offsets int64 [B] (unused)
//  4 ft_white f32 [NUM_EMB,256]    5 ft_black f32 [NUM_EMB,256]
//  6 fc1_w f32 [32,512]  7 fc1_b [32]
//  8 fc2_w f32 [32,32]   9 fc2_b [32]
// 10 fc3_w f32 [1,32]   11 fc3_b [1]
// output f32 [B]

#define H1 256
#define MAXBAG 64
#define MAX_EMB 41025
#define TBL_ELEMS (MAX_EMB * H1)       // 10,502,400 halves per table
#define MAX_B 16384
#define X_ELEMS (MAX_B * 2 * H1)       // fp16 activations

__device__ __half g_ftw16[TBL_ELEMS];
__device__ __half g_ftb16[TBL_ELEMS];
__device__ __half g_x[X_ELEMS];

// ---- table conversion: 8 floats -> 8 halves per thread ----
__global__ __launch_bounds__(256)
void convert_tables(const float4* __restrict__ fw,
                    const float4* __restrict__ fb,
                    int total8)
{
    const int i = blockIdx.x * blockDim.x + threadIdx.x;
    if (i >= 2 * total8) return;
    const float4* src;
    __half* dst;
    int j;
    if (i < total8) { src = fw; dst = g_ftw16; j = i; }
    else            { src = fb; dst = g_ftb16; j = i - total8; }
    const float4 a = src[2 * j];
    const float4 c = src[2 * j + 1];
    __half2 h0 = __floats2half2_rn(a.x, a.y);
    __half2 h1 = __floats2half2_rn(a.z, a.w);
    __half2 h2 = __floats2half2_rn(c.x, c.y);
    __half2 h3 = __floats2half2_rn(c.z, c.w);
    uint4 o;
    o.x = *reinterpret_cast<unsigned*>(&h0);
    o.y = *reinterpret_cast<unsigned*>(&h1);
    o.z = *reinterpret_cast<unsigned*>(&h2);
    o.w = *reinterpret_cast<unsigned*>(&h3);
    *reinterpret_cast<uint4*>(dst + 8 * j) = o;
}

__device__ __forceinline__ void acc8_half(const uint4 v, float* a)
{
    const float2 f0 = __half22float2(*reinterpret_cast<const __half2*>(&v.x));
    const float2 f1 = __half22float2(*reinterpret_cast<const __half2*>(&v.y));
    const float2 f2 = __half22float2(*reinterpret_cast<const __half2*>(&v.z));
    const float2 f3 = __half22float2(*reinterpret_cast<const __half2*>(&v.w));
    a[0] += f0.x; a[1] += f0.y; a[2] += f1.x; a[3] += f1.y;
    a[4] += f2.x; a[5] += f2.y; a[6] += f3.x; a[7] += f3.y;
}

// ---- gather: one warp per (position, table-half). Indices shfl-broadcast. ----
template<int BAG>
__global__ __launch_bounds__(256)
void gather_kernel(const int* __restrict__ wi,
                   const int* __restrict__ bi,
                   int B)
{
    const int gwarp = (blockIdx.x * 256 + threadIdx.x) >> 5;
    const int lane  = threadIdx.x & 31;
    const int pos   = gwarp >> 1;
    const int half  = gwarp & 1;
    if (pos >= B) return;

    const int* idx = half ? bi : wi;
    const int myidx = (lane < BAG) ? idx[(size_t)pos * BAG + lane] : 0;

    const __half* table = half ? g_ftb16 : g_ftw16;
    const __half* base  = table + lane * 8;

    float a[8];
    #pragma unroll
    for (int i = 0; i < 8; i++) a[i] = 0.f;

    #pragma unroll
    for (int k = 0; k < BAG; k++) {
        const int r = __shfl_sync(0xffffffffu, myidx, k);
        const uint4 v = *reinterpret_cast<const uint4*>(base + (size_t)r * H1);
        acc8_half(v, a);
    }

    __half2 o0 = __floats2half2_rn(fmaxf(a[0], 0.f), fmaxf(a[1], 0.f));
    __half2 o1 = __floats2half2_rn(fmaxf(a[2], 0.f), fmaxf(a[3], 0.f));
    __half2 o2 = __floats2half2_rn(fmaxf(a[4], 0.f), fmaxf(a[5], 0.f));
    __half2 o3 = __floats2half2_rn(fmaxf(a[6], 0.f), fmaxf(a[7], 0.f));
    uint4 ov;
    ov.x = *reinterpret_cast<unsigned*>(&o0);
    ov.y = *reinterpret_cast<unsigned*>(&o1);
    ov.z = *reinterpret_cast<unsigned*>(&o2);
    ov.w = *reinterpret_cast<unsigned*>(&o3);
    *reinterpret_cast<uint4*>(g_x + (size_t)pos * (2 * H1) + half * H1 + lane * 8) = ov;
}

// ---- MLP: 8 positions per block, x staged to smem, fc1+fc2+fc3 fused ----
#define P2 8
__global__ __launch_bounds__(256, 4)
void mlp_kernel(const float* __restrict__ fc1w,
                const float* __restrict__ fc1b,
                const float* __restrict__ fc2w,
                const float* __restrict__ fc2b,
                const float* __restrict__ fc3w,
                const float* __restrict__ fc3b,
                float* __restrict__ out,
                int B)
{
    const int t = threadIdx.x;
    const int pos0 = blockIdx.x * P2;

    __shared__ __half xs[P2][2 * H1];    // 8KB
    __shared__ float  h1[P2][32];

    // stage x rows (8 x 1KB) : 512 uint4 loads
    for (int i = t; i < P2 * 64; i += 256) {
        const int p = i >> 6, c = i & 63;
        uint4 v = make_uint4(0u, 0u, 0u, 0u);
        if (pos0 + p < B)
            v = reinterpret_cast<const uint4*>(g_x + (size_t)(pos0 + p) * (2 * H1))[c];
        reinterpret_cast<uint4*>(&xs[p][0])[c] = v;
    }
    __syncthreads();

    // fc1: og = group of 4 outputs (0..7), l = k-lane (0..31)
    {
        const int og = t >> 5;
        const int l  = t & 31;
        const float4* w4 = reinterpret_cast<const float4*>(fc1w);

        float acc[P2][4];
        #pragma unroll
        for (int p = 0; p < P2; p++)
            #pragma unroll
            for (int o = 0; o < 4; o++) acc[p][o] = 0.f;

        #pragma unroll
        for (int j = 0; j < 4; j++) {
            const int kc = j * 32 + l;           // float4-chunk index 0..127
            const float4 w0 = w4[(og * 4 + 0) * 128 + kc];
            const float4 w1 = w4[(og * 4 + 1) * 128 + kc];
            const float4 w2 = w4[(og * 4 + 2) * 128 + kc];
            const float4 w3 = w4[(og * 4 + 3) * 128 + kc];
            #pragma unroll
            for (int p = 0; p < P2; p++) {
                const uint2 xv = *reinterpret_cast<const uint2*>(&xs[p][kc * 4]);
                const float2 f01 = __half22float2(*reinterpret_cast<const __half2*>(&xv.x));
                const float2 f23 = __half22float2(*reinterpret_cast<const __half2*>(&xv.y));
                acc[p][0] += f01.x * w0.x + f01.y * w0.y + f23.x * w0.z + f23.y * w0.w;
                acc[p][1] += f01.x * w1.x + f01.y * w1.y + f23.x * w1.z + f23.y * w1.w;
                acc[p][2] += f01.x * w2.x + f01.y * w2.y + f23.x * w2.z + f23.y * w2.w;
                acc[p][3] += f01.x * w3.x + f01.y * w3.y + f23.x * w3.z + f23.y * w3.w;
            }
        }
        #pragma unroll
        for (int p = 0; p < P2; p++)
            #pragma unroll
            for (int o = 0; o < 4; o++) {
                float s = acc[p][o];
                s += __shfl_down_sync(0xffffffffu, s, 16);
                s += __shfl_down_sync(0xffffffffu, s, 8);
                s += __shfl_down_sync(0xffffffffu, s, 4);
                s += __shfl_down_sync(0xffffffffu, s, 2);
                s += __shfl_down_sync(0xffffffffu, s, 1);
                if (l == 0)
                    h1[p][og * 4 + o] = fmaxf(s + fc1b[og * 4 + o], 0.f);
            }
    }
    __syncthreads();

    // fc2 + fc3: one warp per position (8 warps = 256 threads)
    {
        const int p = t >> 5;
        const int o = t & 31;
        float s2 = 0.f;
        #pragma unroll
        for (int k = 0; k < 32; k++) s2 += h1[p][k] * fc2w[o * 32 + k];
        const float h2 = fmaxf(s2 + fc2b[o], 0.f);
        float v = h2 * fc3w[o];
        #pragma unroll
        for (int off = 16; off > 0; off >>= 1)
            v += __shfl_down_sync(0xffffffffu, v, off);
        if (o == 0 && pos0 + p < B) out[pos0 + p] = v + fc3b[0];
    }
}

// ---- fallback: fully fused fp32 (odd shapes only) ----
#define PF 4
__global__ __launch_bounds__(256, 4)
void nnue_fused_f32(const int* __restrict__ wi, const int* __restrict__ bi,
                    const float* __restrict__ ftw, const float* __restrict__ ftb,
                    const float* __restrict__ fc1w, const float* __restrict__ fc1b,
                    const float* __restrict__ fc2w, const float* __restrict__ fc2b,
                    const float* __restrict__ fc3w, const float* __restrict__ fc3b,
                    float* __restrict__ out, int bag, int B)
{
    const int t = threadIdx.x;
    const int pos0 = blockIdx.x * PF;
    __shared__ int   sW[PF][MAXBAG];
    __shared__ int   sB[PF][MAXBAG];
    __shared__ float x[PF][2 * H1];
    __shared__ float h1[PF][32];

    for (int i = t; i < PF * bag; i += 256) {
        const int p = i / bag, k = i - p * bag;
        if (pos0 + p < B) {
            const size_t g = (size_t)(pos0 + p) * bag + k;
            sW[p][k] = wi[g]; sB[p][k] = bi[g];
        } else { sW[p][k] = 0; sB[p][k] = 0; }
    }
    __syncthreads();
    {
        const int p  = t >> 6;
        const int c4 = t & 63;
        const float* tw = ftw + (size_t)c4 * 4;
        const float* tb = ftb + (size_t)c4 * 4;
        float4 aw = make_float4(0,0,0,0), ab = make_float4(0,0,0,0);
        for (int k = 0; k < bag; k++) {
            const float4 vw = *reinterpret_cast<const float4*>(tw + (size_t)sW[p][k] * H1);
            const float4 vb = *reinterpret_cast<const float4*>(tb + (size_t)sB[p][k] * H1);
            aw.x += vw.x; aw.y += vw.y; aw.z += vw.z; aw.w += vw.w;
            ab.x += vb.x; ab.y += vb.y; ab.z += vb.z; ab.w += vb.w;
        }
        reinterpret_cast<float4*>(&x[p][0])[c4]  = make_float4(fmaxf(aw.x,0.f),fmaxf(aw.y,0.f),fmaxf(aw.z,0.f),fmaxf(aw.w,0.f));
        reinterpret_cast<float4*>(&x[p][H1])[c4] = make_float4(fmaxf(ab.x,0.f),fmaxf(ab.y,0.f),fmaxf(ab.z,0.f),fmaxf(ab.w,0.f));
    }
    __syncthreads();
    {
        const int og = t >> 5, l = t & 31;
        const float4* w4 = reinterpret_cast<const float4*>(fc1w);
        float acc[PF][4];
        for (int p = 0; p < PF; p++) for (int o = 0; o < 4; o++) acc[p][o] = 0.f;
        for (int j = 0; j < 4; j++) {
            const int k = j * 32 + l;
            const float4 w0 = w4[(og*4+0)*128+k], w1 = w4[(og*4+1)*128+k];
            const float4 w2 = w4[(og*4+2)*128+k], w3 = w4[(og*4+3)*128+k];
            for (int p = 0; p < PF; p++) {
                const float4 xv = reinterpret_cast<const float4*>(&x[p][0])[k];
                acc[p][0] += xv.x*w0.x+xv.y*w0.y+xv.z*w0.z+xv.w*w0.w;
                acc[p][1] += xv.x*w1.x+xv.y*w1.y+xv.z*w1.z+xv.w*w1.w;
                acc[p][2] += xv.x*w2.x+xv.y*w2.y+xv.z*w2.z+xv.w*w2.w;
                acc[p][3] += xv.x*w3.x+xv.y*w3.y+xv.z*w3.z+xv.w*w3.w;
            }
        }
        for (int p = 0; p < PF; p++)
            for (int o = 0; o < 4; o++) {
                float s = acc[p][o];
                s += __shfl_down_sync(0xffffffffu, s, 16);
                s += __shfl_down_sync(0xffffffffu, s, 8);
                s += __shfl_down_sync(0xffffffffu, s, 4);
                s += __shfl_down_sync(0xffffffffu, s, 2);
                s += __shfl_down_sync(0xffffffffu, s, 1);
                if (l == 0) h1[p][og*4+o] = fmaxf(s + fc1b[og*4+o], 0.f);
            }
    }
    __syncthreads();
    if (t < 32 * PF) {
        const int p = t >> 5, o = t & 31;
        float s2 = 0.f;
        for (int k = 0; k < 32; k++) s2 += h1[p][k] * fc2w[o*32+k];
        const float h2 = fmaxf(s2 + fc2b[o], 0.f);
        float v = h2 * fc3w[o];
        for (int off = 16; off > 0; off >>= 1) v += __shfl_down_sync(0xffffffffu, v, off);
        if (o == 0 && pos0 + p < B) out[pos0 + p] = v + fc3b[0];
    }
}

extern "C" void kernel_launch(void* const* d_in, const int* in_sizes, int n_in,
                              void* d_out, int out_size)
{
    const int*   wi   = (const int*)  d_in[0];
    const int*   bi   = (const int*)  d_in[2];
    const float* ftw  = (const float*)d_in[4];
    const float* ftb  = (const float*)d_in[5];
    const float* fc1w = (const float*)d_in[6];
    const float* fc1b = (const float*)d_in[7];
    const float* fc2w = (const float*)d_in[8];
    const float* fc2b = (const float*)d_in[9];
    const float* fc3w = (const float*)d_in[10];
    const float* fc3b = (const float*)d_in[11];
    float* out = (float*)d_out;

    const int B   = in_sizes[1];
    const int bag = in_sizes[0] / B;          // 30
    const int tblElems = in_sizes[4];

    if (bag == 30 && B <= MAX_B &&
        tblElems <= TBL_ELEMS && in_sizes[5] <= TBL_ELEMS && (tblElems % 8) == 0) {
        const int total8 = tblElems / 8;
        const int cgrid = (2 * total8 + 255) / 256;
        convert_tables<<<cgrid, 256>>>((const float4*)ftw, (const float4*)ftb, total8);

        const int gwarps = 2 * B;                       // (pos, half) tasks
        const int ggrid  = (gwarps * 32 + 255) / 256;
        gather_kernel<30><<<ggrid, 256>>>(wi, bi, B);

        const int mgrid = (B + P2 - 1) / P2;
        mlp_kernel<<<mgrid, 256>>>(fc1w, fc1b, fc2w, fc2b, fc3w, fc3b, out, B);
    } else {
        const int grid = (B + PF - 1) / PF;
        nnue_fused_f32<<<grid, 256>>>(wi, bi, ftw, ftb,
            fc1w, fc1b, fc2w, fc2b, fc3w, fc3b, out, bag, B);
    }
}